// round 13
// baseline (speedup 1.0000x reference)
#include <cuda_runtime.h>
#include <cuda_fp16.h>
#include <math.h>
#include <stdint.h>

// Problem constants
#define NN 50000
#define EE 800000
#define F_IN 512
#define HH 128
#define CC 16
#define LD3H 384   // 3*H

// ---------------- device scratch (static, no allocations) ----------------
__device__ int    g_count[NN];
__device__ int    g_rowptr[NN + 1];
__device__ int    g_pos[NN];
__device__ int    g_bsum[64];
__device__ int2   g_cv[EE];                    // packed (col, val bits)
__device__ __half g_a1h[(size_t)NN * LD3H];    // a1 in fp16 (ld 384)
__device__ __half g_g2h[(size_t)NN * LD3H];    // stage-2 result in fp16 (ld 384)
__device__ __half g_h16B[(size_t)NN * 256];    // GEMM out blocks 1,2 (fp16, ld 256)
__device__ __half g_h16C[(size_t)NN * 128];    // mid-hop block2 (fp16, ld 128)
__device__ __half g_w1h[3 * 128 * F_IN];       // w1^T fp16 [3][128 n][512 k]
__device__ __half g_w2h[3 * 128 * LD3H];       // w2^T fp16 [3][128 n][384 k]

// ---------------- helpers ----------------
__device__ __forceinline__ void mma_f16(float* c, const uint32_t* a, const uint32_t* b) {
    asm volatile(
        "mma.sync.aligned.m16n8k16.row.col.f32.f16.f16.f32 "
        "{%0,%1,%2,%3}, {%4,%5,%6,%7}, {%8,%9}, {%0,%1,%2,%3};\n"
        : "+f"(c[0]), "+f"(c[1]), "+f"(c[2]), "+f"(c[3])
        : "r"(a[0]), "r"(a[1]), "r"(a[2]), "r"(a[3]), "r"(b[0]), "r"(b[1]));
}

__device__ __forceinline__ uint32_t pack_h2(float lo, float hi) {
    uint32_t r;
    asm("cvt.rn.f16x2.f32 %0, %1, %2;" : "=r"(r) : "f"(hi), "f"(lo));
    return r;
}

__device__ __forceinline__ void cpa16(uint32_t dst_smem, const void* src, int valid) {
    asm volatile("cp.async.cg.shared.global [%0], [%1], 16, %2;\n"
                 :: "r"(dst_smem), "l"(src), "r"(valid ? 16 : 0));
}
__device__ __forceinline__ void cpa_commit() { asm volatile("cp.async.commit_group;\n"); }
__device__ __forceinline__ void cpa_wait0()  { asm volatile("cp.async.wait_group 0;\n"); }

// ---------------- prep: W1 and W2 [3][K][128] -> W^T fp16 [3][128][K] ----------------
__global__ void k_wth2(const float* __restrict__ W1, const float* __restrict__ W2)
{
    __shared__ float t[32][33];
    int zz = blockIdx.z;
    int is2 = zz >= 3;
    int z  = is2 ? zz - 3 : zz;
    int K  = is2 ? LD3H : F_IN;
    const float* W = is2 ? W2 : W1;
    __half* WT = is2 ? g_w2h : g_w1h;
    int k0 = blockIdx.x * 32;
    if (k0 >= K) return;
    int n0 = blockIdx.y * 32;
    int tx = threadIdx.x, ty = threadIdx.y;  // 32 x 8
    #pragma unroll
    for (int i = 0; i < 4; i++) {
        int k = k0 + ty + i * 8;
        t[ty + i * 8][tx] = W[(size_t)z * K * 128 + (size_t)k * 128 + n0 + tx];
    }
    __syncthreads();
    #pragma unroll
    for (int i = 0; i < 4; i++) {
        int n = n0 + ty + i * 8;
        WT[(size_t)z * 128 * K + (size_t)n * K + k0 + tx] = __float2half_rn(t[tx][ty + i * 8]);
    }
}

// ---------------- CSR build (3-kernel scan) ----------------
__global__ void k_zero_counts() {
    int i = blockIdx.x * blockDim.x + threadIdx.x;
    if (i < NN) g_count[i] = 0;
}

__global__ void k_count(const int* __restrict__ idx) {
    int e = blockIdx.x * blockDim.x + threadIdx.x;
    if (e < EE) atomicAdd(&g_count[idx[e]], 1);
}

#define SCAN_B 1024
__global__ void k_scan1() {
    __shared__ int s[SCAN_B];
    int t = threadIdx.x;
    int i = blockIdx.x * SCAN_B + t;
    int v = (i < NN) ? g_count[i] : 0;
    s[t] = v;
    __syncthreads();
    #pragma unroll
    for (int o = 1; o < SCAN_B; o <<= 1) {
        int u = (t >= o) ? s[t - o] : 0;
        __syncthreads();
        s[t] += u;
        __syncthreads();
    }
    if (i < NN) g_rowptr[i] = s[t] - v;
    if (t == SCAN_B - 1) g_bsum[blockIdx.x] = s[t];
}

__global__ void k_scan2(int nblk) {
    int lane = threadIdx.x;
    int carry = 0;
    for (int base = 0; base < nblk; base += 32) {
        int i = base + lane;
        int v = (i < nblk) ? g_bsum[i] : 0;
        int incl = v;
        #pragma unroll
        for (int o = 1; o < 32; o <<= 1) {
            int u = __shfl_up_sync(0xffffffffu, incl, o);
            if (lane >= o) incl += u;
        }
        if (i < nblk) g_bsum[i] = carry + incl - v;
        carry += __shfl_sync(0xffffffffu, incl, 31);
    }
}

__global__ void k_scan3() {
    int i = blockIdx.x * SCAN_B + threadIdx.x;
    if (i < NN) {
        int v = g_rowptr[i] + g_bsum[blockIdx.x];
        g_rowptr[i] = v;
        g_pos[i] = v;
    }
    if (i == 0) g_rowptr[NN] = EE;
}

__global__ void k_scatter(const int* __restrict__ idx, const float* __restrict__ vals) {
    int e = blockIdx.x * blockDim.x + threadIdx.x;
    if (e < EE) {
        int r = idx[e];
        int p = atomicAdd(&g_pos[r], 1);
        g_cv[p] = make_int2(idx[EE + e], __float_as_int(vals[e]));
    }
}

// ---------------- GEMM1: A fp32 (x) direct, cvt-in-fragment; BK=32 ----------------
#define X_ALDF 36                              // floats per A smem row (32+4)
#define X_ABUF (128 * X_ALDF)                  // floats per A buffer
#define X_BLD  40                              // halves per B smem row (32+8)
#define X_BBUF (128 * X_BLD)                   // halves per B buffer
#define GX_SMEM_BYTES (2 * X_ABUF * 4 + 2 * X_BBUF * 2)   // 36864 + 20480 = 57344

__global__ __launch_bounds__(256, 2)
void k_gemm1x(const float* __restrict__ A,
              const __half* __restrict__ Bt,
              const float* __restrict__ bias,
              __half* __restrict__ C0h,
              __half* __restrict__ Hout,
              int M)
{
    extern __shared__ float smx[];
    float* As = smx;                               // [2][128][X_ALDF]
    __half* Bs = (__half*)(smx + 2 * X_ABUF);      // [2][128][X_BLD]

    const int K = F_IN;
    const int nb = blockIdx.x;
    const __half* B = Bt + (size_t)nb * 128 * K;
    const float* bi = bias + nb * 128;

    const int m0   = blockIdx.y * 128;
    const int tid  = threadIdx.x;
    const int lane = tid & 31;
    const int wid  = tid >> 5;
    const int wm0  = (wid & 1) * 64;
    const int wn0  = (wid >> 1) * 32;
    const int gp   = lane >> 2;
    const int tg   = lane & 3;

    float acc[4][4][4];
    #pragma unroll
    for (int i = 0; i < 4; i++)
        #pragma unroll
        for (int j = 0; j < 4; j++)
            #pragma unroll
            for (int q = 0; q < 4; q++) acc[i][j][q] = 0.f;

    const int nk = K >> 5;   // 16

    auto stage = [&](int kt, int buf) {
        const int k0 = kt << 5;
        uint32_t abase = (uint32_t)__cvta_generic_to_shared(As + buf * X_ABUF);
        uint32_t bbase = (uint32_t)__cvta_generic_to_shared(Bs + buf * X_BBUF);
        #pragma unroll
        for (int s = 0; s < 4; s++) {
            int idx = s * 256 + tid;          // 0..1023
            int r = idx >> 3;                 // 0..127
            int c = (idx & 7) * 4;            // floats 0..28
            int gr = m0 + r;
            int ok = gr < M;
            int sr = ok ? gr : (M - 1);
            cpa16(abase + (r * X_ALDF + c) * 4, A + (size_t)sr * K + k0 + c, ok);
        }
        #pragma unroll
        for (int s = 0; s < 2; s++) {
            int idx = s * 256 + tid;          // 0..511
            int r = idx >> 2;                 // 0..127
            int c = (idx & 3) * 8;            // halves 0..24
            cpa16(bbase + (r * X_BLD + c) * 2, B + (size_t)r * K + k0 + c, 1);
        }
        cpa_commit();
    };

    stage(0, 0);

    for (int kt = 0; kt < nk; kt++) {
        cpa_wait0();
        __syncthreads();
        if (kt + 1 < nk) stage(kt + 1, (kt + 1) & 1);

        const float* Ab = As + (kt & 1) * X_ABUF;
        const __half* Bb = Bs + (kt & 1) * X_BBUF;

        #pragma unroll
        for (int ks = 0; ks < 2; ks++) {
            const int kk = ks * 16 + 2 * tg;
            uint32_t af[4][4], bf[4][2];
            #pragma unroll
            for (int i = 0; i < 4; i++) {
                int r = wm0 + i * 16 + gp;
                float2 v0 = *(const float2*)&Ab[r * X_ALDF + kk];
                float2 v1 = *(const float2*)&Ab[(r + 8) * X_ALDF + kk];
                float2 v2 = *(const float2*)&Ab[r * X_ALDF + kk + 8];
                float2 v3 = *(const float2*)&Ab[(r + 8) * X_ALDF + kk + 8];
                af[i][0] = pack_h2(v0.x, v0.y);
                af[i][1] = pack_h2(v1.x, v1.y);
                af[i][2] = pack_h2(v2.x, v2.y);
                af[i][3] = pack_h2(v3.x, v3.y);
            }
            #pragma unroll
            for (int j = 0; j < 4; j++) {
                int n = wn0 + j * 8 + gp;
                bf[j][0] = *(const uint32_t*)&Bb[n * X_BLD + kk];
                bf[j][1] = *(const uint32_t*)&Bb[n * X_BLD + kk + 8];
            }
            #pragma unroll
            for (int i = 0; i < 4; i++)
                #pragma unroll
                for (int j = 0; j < 4; j++)
                    mma_f16(acc[i][j], af[i], bf[j]);
        }
        __syncthreads();
    }

    #pragma unroll
    for (int i = 0; i < 4; i++) {
        #pragma unroll
        for (int rr = 0; rr < 2; rr++) {
            int row = m0 + wm0 + i * 16 + gp + rr * 8;
            if (row >= M) continue;
            #pragma unroll
            for (int j = 0; j < 4; j++) {
                int col = wn0 + j * 8 + 2 * tg;
                float2 v;
                v.x = fmaxf(acc[i][j][rr * 2 + 0] + bi[col], 0.f);
                v.y = fmaxf(acc[i][j][rr * 2 + 1] + bi[col + 1], 0.f);
                __half2 h = __floats2half2_rn(v.x, v.y);
                if (nb == 0) {
                    *(__half2*)(C0h + (size_t)row * LD3H + col) = h;
                } else {
                    *(__half2*)(Hout + (size_t)row * 256 + (nb - 1) * 128 + col) = h;
                }
            }
        }
    }
}

// ---------------- GEMM2: all-fp16 (m16n8k16), BK=64, double-buffered ----------------
#define AH_LD 72
#define AH_BUF (128 * AH_LD)
#define GH_SMEM_BYTES (4 * AH_BUF * 2)  // 73728 B

__global__ __launch_bounds__(256, 2)
void k_gemm_h(const __half* __restrict__ A, int lda,
              const __half* __restrict__ Bt,
              __half* __restrict__ C0h,
              __half* __restrict__ Hout,
              int M, int K)
{
    extern __shared__ __half smh[];
    __half* As = smh;
    __half* Bs = smh + 2 * AH_BUF;

    const int nb = blockIdx.x;
    const __half* B = Bt + (size_t)nb * 128 * K;

    const int m0   = blockIdx.y * 128;
    const int tid  = threadIdx.x;
    const int lane = tid & 31;
    const int wid  = tid >> 5;
    const int wm0  = (wid & 1) * 64;
    const int wn0  = (wid >> 1) * 32;
    const int gp   = lane >> 2;
    const int tg   = lane & 3;

    float acc[4][4][4];
    #pragma unroll
    for (int i = 0; i < 4; i++)
        #pragma unroll
        for (int j = 0; j < 4; j++)
            #pragma unroll
            for (int q = 0; q < 4; q++) acc[i][j][q] = 0.f;

    const int nk = K >> 6;

    auto stage = [&](int kt, int buf) {
        const int k0 = kt << 6;
        uint32_t abase = (uint32_t)__cvta_generic_to_shared(As + buf * AH_BUF);
        uint32_t bbase = (uint32_t)__cvta_generic_to_shared(Bs + buf * AH_BUF);
        #pragma unroll
        for (int s = 0; s < 4; s++) {
            int idx = s * 256 + tid;
            int r = idx >> 3;
            int c = (idx & 7) * 8;
            int gr = m0 + r;
            int ok = gr < M;
            int sr = ok ? gr : (M - 1);
            cpa16(abase + (r * AH_LD + c) * 2, A + (size_t)sr * lda + k0 + c, ok);
        }
        #pragma unroll
        for (int s = 0; s < 4; s++) {
            int idx = s * 256 + tid;
            int r = idx >> 3;
            int c = (idx & 7) * 8;
            cpa16(bbase + (r * AH_LD + c) * 2, B + (size_t)r * K + k0 + c, 1);
        }
        cpa_commit();
    };

    stage(0, 0);

    for (int kt = 0; kt < nk; kt++) {
        cpa_wait0();
        __syncthreads();
        if (kt + 1 < nk) stage(kt + 1, (kt + 1) & 1);

        const __half* Ab = As + (kt & 1) * AH_BUF;
        const __half* Bb = Bs + (kt & 1) * AH_BUF;

        #pragma unroll
        for (int ks = 0; ks < 4; ks++) {
            const int kk = ks * 16 + 2 * tg;
            uint32_t af[4][4], bf[4][2];
            #pragma unroll
            for (int i = 0; i < 4; i++) {
                int r = wm0 + i * 16 + gp;
                af[i][0] = *(const uint32_t*)&Ab[r * AH_LD + kk];
                af[i][1] = *(const uint32_t*)&Ab[(r + 8) * AH_LD + kk];
                af[i][2] = *(const uint32_t*)&Ab[r * AH_LD + kk + 8];
                af[i][3] = *(const uint32_t*)&Ab[(r + 8) * AH_LD + kk + 8];
            }
            #pragma unroll
            for (int j = 0; j < 4; j++) {
                int n = wn0 + j * 8 + gp;
                bf[j][0] = *(const uint32_t*)&Bb[n * AH_LD + kk];
                bf[j][1] = *(const uint32_t*)&Bb[n * AH_LD + kk + 8];
            }
            #pragma unroll
            for (int i = 0; i < 4; i++)
                #pragma unroll
                for (int j = 0; j < 4; j++)
                    mma_f16(acc[i][j], af[i], bf[j]);
        }
        __syncthreads();
    }

    #pragma unroll
    for (int i = 0; i < 4; i++) {
        #pragma unroll
        for (int rr = 0; rr < 2; rr++) {
            int row = m0 + wm0 + i * 16 + gp + rr * 8;
            if (row >= M) continue;
            #pragma unroll
            for (int j = 0; j < 4; j++) {
                int col = wn0 + j * 8 + 2 * tg;
                __half2 h = __floats2half2_rn(acc[i][j][rr * 2 + 0], acc[i][j][rr * 2 + 1]);
                if (nb == 0) {
                    *(__half2*)(C0h + (size_t)row * LD3H + col) = h;
                } else {
                    *(__half2*)(Hout + (size_t)row * 256 + (nb - 1) * 128 + col) = h;
                }
            }
        }
    }
}

// ---------------- SpMM (CSR gather, fp16 sources, packed col/val) ----------------
#define ACC8(av, hv, vv) do { \
    const __half2* _h = (const __half2*)&(hv); \
    _Pragma("unroll") \
    for (int _k = 0; _k < 4; _k++) { \
        float2 _f = __half22float2(_h[_k]); \
        (av)[2 * _k]     = fmaf((vv), _f.x, (av)[2 * _k]); \
        (av)[2 * _k + 1] = fmaf((vv), _f.y, (av)[2 * _k + 1]); \
    } \
} while (0)

__global__ void k_spmm256t(const __half* __restrict__ src,
                           __half* __restrict__ dstH1, __half* __restrict__ dstH2)
{
    int warp = (blockIdx.x * blockDim.x + threadIdx.x) >> 5;
    int lane = threadIdx.x & 31;
    if (warp >= NN) return;
    int s = g_rowptr[warp];
    int e = g_rowptr[warp + 1];
    float a[8];
    #pragma unroll
    for (int q = 0; q < 8; q++) a[q] = 0.f;
    int p = s;
    for (; p + 7 < e; p += 8) {
        int2 cv0 = g_cv[p],     cv1 = g_cv[p + 1];
        int2 cv2 = g_cv[p + 2], cv3 = g_cv[p + 3];
        int2 cv4 = g_cv[p + 4], cv5 = g_cv[p + 5];
        int2 cv6 = g_cv[p + 6], cv7 = g_cv[p + 7];
        uint4 q0 = *(const uint4*)(src + (size_t)cv0.x * 256 + lane * 8);
        uint4 q1 = *(const uint4*)(src + (size_t)cv1.x * 256 + lane * 8);
        uint4 q2 = *(const uint4*)(src + (size_t)cv2.x * 256 + lane * 8);
        uint4 q3 = *(const uint4*)(src + (size_t)cv3.x * 256 + lane * 8);
        uint4 q4 = *(const uint4*)(src + (size_t)cv4.x * 256 + lane * 8);
        uint4 q5 = *(const uint4*)(src + (size_t)cv5.x * 256 + lane * 8);
        uint4 q6 = *(const uint4*)(src + (size_t)cv6.x * 256 + lane * 8);
        uint4 q7 = *(const uint4*)(src + (size_t)cv7.x * 256 + lane * 8);
        ACC8(a, q0, __int_as_float(cv0.y)); ACC8(a, q1, __int_as_float(cv1.y));
        ACC8(a, q2, __int_as_float(cv2.y)); ACC8(a, q3, __int_as_float(cv3.y));
        ACC8(a, q4, __int_as_float(cv4.y)); ACC8(a, q5, __int_as_float(cv5.y));
        ACC8(a, q6, __int_as_float(cv6.y)); ACC8(a, q7, __int_as_float(cv7.y));
    }
    for (; p + 1 < e; p += 2) {
        int2 cv0 = g_cv[p], cv1 = g_cv[p + 1];
        uint4 q0 = *(const uint4*)(src + (size_t)cv0.x * 256 + lane * 8);
        uint4 q1 = *(const uint4*)(src + (size_t)cv1.x * 256 + lane * 8);
        ACC8(a, q0, __int_as_float(cv0.y)); ACC8(a, q1, __int_as_float(cv1.y));
    }
    if (p < e) {
        int2 cv0 = g_cv[p];
        uint4 q0 = *(const uint4*)(src + (size_t)cv0.x * 256 + lane * 8);
        ACC8(a, q0, __int_as_float(cv0.y));
    }
    __half2 h[4];
    #pragma unroll
    for (int k = 0; k < 4; k++) h[k] = __floats2half2_rn(a[2 * k], a[2 * k + 1]);
    if (lane < 16) {
        *(uint4*)(dstH1 + (size_t)warp * LD3H + lane * 8) = *(uint4*)h;
    } else {
        *(uint4*)(dstH2 + (size_t)warp * 128 + (lane - 16) * 8) = *(uint4*)h;
    }
}

__global__ void k_spmm128t(const __half* __restrict__ src, __half* __restrict__ dstH)
{
    int warp = (blockIdx.x * blockDim.x + threadIdx.x) >> 5;
    int lane = threadIdx.x & 31;
    int row = 2 * warp + (lane >> 4);
    int sub = lane & 15;
    if (row >= NN) return;
    int s = g_rowptr[row];
    int e = g_rowptr[row + 1];
    float a[8];
    #pragma unroll
    for (int q = 0; q < 8; q++) a[q] = 0.f;
    int p = s;
    for (; p + 3 < e; p += 4) {
        int2 cv0 = g_cv[p],     cv1 = g_cv[p + 1];
        int2 cv2 = g_cv[p + 2], cv3 = g_cv[p + 3];
        uint4 q0 = *(const uint4*)(src + (size_t)cv0.x * 128 + sub * 8);
        uint4 q1 = *(const uint4*)(src + (size_t)cv1.x * 128 + sub * 8);
        uint4 q2 = *(const uint4*)(src + (size_t)cv2.x * 128 + sub * 8);
        uint4 q3 = *(const uint4*)(src + (size_t)cv3.x * 128 + sub * 8);
        ACC8(a, q0, __int_as_float(cv0.y)); ACC8(a, q1, __int_as_float(cv1.y));
        ACC8(a, q2, __int_as_float(cv2.y)); ACC8(a, q3, __int_as_float(cv3.y));
    }
    for (; p < e; p++) {
        int2 cv0 = g_cv[p];
        uint4 q0 = *(const uint4*)(src + (size_t)cv0.x * 128 + sub * 8);
        ACC8(a, q0, __int_as_float(cv0.y));
    }
    __half2 h[4];
    #pragma unroll
    for (int k = 0; k < 4; k++) h[k] = __floats2half2_rn(a[2 * k], a[2 * k + 1]);
    *(uint4*)(dstH + (size_t)row * LD3H + sub * 8) = *(uint4*)h;
}

// ---------------- final: out = log_softmax((g2h + b2cat) @ wf + bf), fp16 input ----------------
#define FROWS 8
__global__ __launch_bounds__(128)
void k_final16(const __half* __restrict__ g,
               const float* __restrict__ b2,
               const float* __restrict__ wf,
               const float* __restrict__ bfv,
               float* __restrict__ out)
{
    __shared__ float wfs[LD3H * CC];
    __shared__ float gs[FROWS][LD3H];
    int tid = threadIdx.x;
    for (int i = tid; i < LD3H * CC; i += 128) wfs[i] = wf[i];
    int row0 = blockIdx.x * FROWS;
    for (int j = tid; j < FROWS * LD3H / 2; j += 128) {
        int r = j / (LD3H / 2);
        int c = 2 * (j % (LD3H / 2));
        int gr = row0 + r;
        float2 f = make_float2(0.f, 0.f);
        if (gr < NN) {
            __half2 h = *(const __half2*)(g + (size_t)gr * LD3H + c);
            f = __half22float2(h);
            f.x += b2[c];
            f.y += b2[c + 1];
        }
        gs[r][c] = f.x;
        gs[r][c + 1] = f.y;
    }
    __syncthreads();

    int r = tid >> 4;
    int c = tid & 15;
    float acc = bfv[c];
    #pragma unroll 8
    for (int k = 0; k < LD3H; k++) acc = fmaf(gs[r][k], wfs[k * CC + c], acc);

    float m = acc;
    #pragma unroll
    for (int o = 8; o >= 1; o >>= 1) m = fmaxf(m, __shfl_xor_sync(0xffffffffu, m, o, 16));
    float ex = __expf(acc - m);
    float s = ex;
    #pragma unroll
    for (int o = 8; o >= 1; o >>= 1) s += __shfl_xor_sync(0xffffffffu, s, o, 16);
    int gr = row0 + r;
    if (gr < NN) out[gr * CC + c] = acc - m - logf(s);
}

// ---------------- launch ----------------
extern "C" void kernel_launch(void* const* d_in, const int* in_sizes, int n_in,
                              void* d_out, int out_size)
{
    const float* x   = (const float*)d_in[0];
    const int*   adj = (const int*)d_in[1];
    const float* av  = (const float*)d_in[2];
    const float* w1  = (const float*)d_in[3];
    const float* b1  = (const float*)d_in[4];
    const float* w2  = (const float*)d_in[5];
    const float* b2  = (const float*)d_in[6];
    const float* wf  = (const float*)d_in[7];
    const float* bf  = (const float*)d_in[8];
    float* out = (float*)d_out;

    __half *a1h, *g2h, *h16B, *h16C, *w1h, *w2h;
    cudaGetSymbolAddress((void**)&a1h,  g_a1h);
    cudaGetSymbolAddress((void**)&g2h,  g_g2h);
    cudaGetSymbolAddress((void**)&h16B, g_h16B);
    cudaGetSymbolAddress((void**)&h16C, g_h16C);
    cudaGetSymbolAddress((void**)&w1h,  g_w1h);
    cudaGetSymbolAddress((void**)&w2h,  g_w2h);

    cudaFuncSetAttribute(k_gemm1x, cudaFuncAttributeMaxDynamicSharedMemorySize,
                         GX_SMEM_BYTES);
    cudaFuncSetAttribute(k_gemm_h, cudaFuncAttributeMaxDynamicSharedMemorySize,
                         GH_SMEM_BYTES);

    static cudaStream_t s2 = 0;
    static cudaEvent_t evFork = 0, evW = 0, evCSR = 0;
    if (!s2) {
        cudaStreamCreateWithFlags(&s2, cudaStreamNonBlocking);
        cudaEventCreateWithFlags(&evFork, cudaEventDisableTiming);
        cudaEventCreateWithFlags(&evW,    cudaEventDisableTiming);
        cudaEventCreateWithFlags(&evCSR,  cudaEventDisableTiming);
    }

    const int nscan = (NN + SCAN_B - 1) / SCAN_B;   // 49
    const int mtiles = (NN + 127) / 128;            // 391
    const int sblocks = (NN + 3) / 4;               // spmm256: warp per row
    const int sblocks2 = (NN / 2 + 3) / 4;          // spmm128: warp per 2 rows

    // ---- fork: weights then CSR on s2 (fast scan keeps the chain ~56 us) ----
    cudaEventRecord(evFork, 0);
    cudaStreamWaitEvent(s2, evFork, 0);
    k_wth2<<<dim3(F_IN / 32, 4, 6), dim3(32, 8), 0, s2>>>(w1, w2);
    cudaEventRecord(evW, s2);
    k_zero_counts<<<(NN + 255) / 256, 256, 0, s2>>>();
    k_count<<<(EE + 255) / 256, 256, 0, s2>>>(adj);
    k_scan1<<<nscan, SCAN_B, 0, s2>>>();
    k_scan2<<<1, 32, 0, s2>>>(nscan);
    k_scan3<<<nscan, SCAN_B, 0, s2>>>();
    k_scatter<<<(EE + 255) / 256, 256, 0, s2>>>(adj, av);
    cudaEventRecord(evCSR, s2);

    // s0: GEMM1 reads fp32 x directly (no xhalf prep)
    cudaStreamWaitEvent(0, evW, 0);
    k_gemm1x<<<dim3(3, mtiles), 256, GX_SMEM_BYTES>>>(
        x, w1h, b1, a1h, h16B, NN);

    // join: spmm needs CSR
    cudaStreamWaitEvent(0, evCSR, 0);

    // stage-1 hops
    k_spmm256t<<<sblocks, 128>>>(h16B, a1h + HH, h16C);
    k_spmm128t<<<sblocks2, 128>>>(h16C, a1h + 2 * HH);

    // GEMM2: block0 -> g2h; blocks 1,2 -> h16B (bias deferred)
    k_gemm_h<<<dim3(3, mtiles), 256, GH_SMEM_BYTES>>>(
        a1h, LD3H, w2h, g2h, h16B, NN, LD3H);

    // stage-2 hops
    k_spmm256t<<<sblocks, 128>>>(h16B, g2h + HH, h16C);
    k_spmm128t<<<sblocks2, 128>>>(h16C, g2h + 2 * HH);

    // final (fp16 input, bias b2 added here in fp32)
    k_final16<<<(NN + FROWS - 1) / FROWS, 128>>>(g2h, b2, wf, bf, out);

    (void)in_sizes; (void)n_in; (void)out_size;
}

// round 14
// speedup vs baseline: 1.0883x; 1.0883x over previous
#include <cuda_runtime.h>
#include <cuda_fp16.h>
#include <math.h>
#include <stdint.h>

// Problem constants
#define NN 50000
#define EE 800000
#define F_IN 512
#define HH 128
#define CC 16
#define LD3H 384   // 3*H

// ---------------- device scratch (static, no allocations) ----------------
__device__ int    g_count[NN];
__device__ int    g_rowptr[NN + 1];
__device__ int    g_pos[NN];
__device__ int    g_bsum[64];
__device__ int2   g_cv[EE];                    // packed (col, val bits)
__device__ __half g_xh[(size_t)NN * F_IN];     // x in fp16
__device__ __half g_a1h[(size_t)NN * LD3H];    // a1 in fp16 (ld 384)
__device__ __half g_g2h[(size_t)NN * LD3H];    // stage-2 result in fp16 (ld 384)
__device__ __half g_h16B[(size_t)NN * 256];    // GEMM out blocks 1,2 (fp16, ld 256)
__device__ __half g_h16C[(size_t)NN * 128];    // mid-hop block2 (fp16, ld 128)
__device__ __half g_w1h[3 * 128 * F_IN];       // w1^T fp16 [3][128 n][512 k]
__device__ __half g_w2h[3 * 128 * LD3H];       // w2^T fp16 [3][128 n][384 k]

// ---------------- helpers ----------------
__device__ __forceinline__ void mma_f16(float* c, const uint32_t* a, const uint32_t* b) {
    asm volatile(
        "mma.sync.aligned.m16n8k16.row.col.f32.f16.f16.f32 "
        "{%0,%1,%2,%3}, {%4,%5,%6,%7}, {%8,%9}, {%0,%1,%2,%3};\n"
        : "+f"(c[0]), "+f"(c[1]), "+f"(c[2]), "+f"(c[3])
        : "r"(a[0]), "r"(a[1]), "r"(a[2]), "r"(a[3]), "r"(b[0]), "r"(b[1]));
}

__device__ __forceinline__ void cpa16(uint32_t dst_smem, const void* src, int valid) {
    asm volatile("cp.async.cg.shared.global [%0], [%1], 16, %2;\n"
                 :: "r"(dst_smem), "l"(src), "r"(valid ? 16 : 0));
}
__device__ __forceinline__ void cpa_commit() { asm volatile("cp.async.commit_group;\n"); }
__device__ __forceinline__ void cpa_wait0()  { asm volatile("cp.async.wait_group 0;\n"); }

// ---------------- prep: x -> fp16 ----------------
#define NXE ((size_t)NN * F_IN)   // 25,600,000
__global__ void k_xhalf(const float4* __restrict__ x)
{
    size_t i = (size_t)blockIdx.x * blockDim.x + threadIdx.x;   // 8 floats each
    if (i * 8 >= NXE) return;
    float4 v0 = x[i * 2];
    float4 v1 = x[i * 2 + 1];
    __half2 h[4];
    h[0] = __floats2half2_rn(v0.x, v0.y);
    h[1] = __floats2half2_rn(v0.z, v0.w);
    h[2] = __floats2half2_rn(v1.x, v1.y);
    h[3] = __floats2half2_rn(v1.z, v1.w);
    *(uint4*)(g_xh + i * 8) = *(uint4*)h;
}

// ---------------- prep: W1 and W2 [3][K][128] -> W^T fp16 [3][128][K] ----------------
__global__ void k_wth2(const float* __restrict__ W1, const float* __restrict__ W2)
{
    __shared__ float t[32][33];
    int zz = blockIdx.z;
    int is2 = zz >= 3;
    int z  = is2 ? zz - 3 : zz;
    int K  = is2 ? LD3H : F_IN;
    const float* W = is2 ? W2 : W1;
    __half* WT = is2 ? g_w2h : g_w1h;
    int k0 = blockIdx.x * 32;
    if (k0 >= K) return;
    int n0 = blockIdx.y * 32;
    int tx = threadIdx.x, ty = threadIdx.y;  // 32 x 8
    #pragma unroll
    for (int i = 0; i < 4; i++) {
        int k = k0 + ty + i * 8;
        t[ty + i * 8][tx] = W[(size_t)z * K * 128 + (size_t)k * 128 + n0 + tx];
    }
    __syncthreads();
    #pragma unroll
    for (int i = 0; i < 4; i++) {
        int n = n0 + ty + i * 8;
        WT[(size_t)z * 128 * K + (size_t)n * K + k0 + tx] = __float2half_rn(t[tx][ty + i * 8]);
    }
}

// ---------------- CSR build (3-kernel scan) ----------------
__global__ void k_zero_counts() {
    int i = blockIdx.x * blockDim.x + threadIdx.x;
    if (i < NN) g_count[i] = 0;
}

__global__ void k_count(const int* __restrict__ idx) {
    int e = blockIdx.x * blockDim.x + threadIdx.x;
    if (e < EE) atomicAdd(&g_count[idx[e]], 1);
}

#define SCAN_B 1024
__global__ void k_scan1() {
    __shared__ int s[SCAN_B];
    int t = threadIdx.x;
    int i = blockIdx.x * SCAN_B + t;
    int v = (i < NN) ? g_count[i] : 0;
    s[t] = v;
    __syncthreads();
    #pragma unroll
    for (int o = 1; o < SCAN_B; o <<= 1) {
        int u = (t >= o) ? s[t - o] : 0;
        __syncthreads();
        s[t] += u;
        __syncthreads();
    }
    if (i < NN) g_rowptr[i] = s[t] - v;
    if (t == SCAN_B - 1) g_bsum[blockIdx.x] = s[t];
}

__global__ void k_scan2(int nblk) {
    int lane = threadIdx.x;
    int carry = 0;
    for (int base = 0; base < nblk; base += 32) {
        int i = base + lane;
        int v = (i < nblk) ? g_bsum[i] : 0;
        int incl = v;
        #pragma unroll
        for (int o = 1; o < 32; o <<= 1) {
            int u = __shfl_up_sync(0xffffffffu, incl, o);
            if (lane >= o) incl += u;
        }
        if (i < nblk) g_bsum[i] = carry + incl - v;
        carry += __shfl_sync(0xffffffffu, incl, 31);
    }
}

__global__ void k_scan3() {
    int i = blockIdx.x * SCAN_B + threadIdx.x;
    if (i < NN) {
        int v = g_rowptr[i] + g_bsum[blockIdx.x];
        g_rowptr[i] = v;
        g_pos[i] = v;
    }
    if (i == 0) g_rowptr[NN] = EE;
}

__global__ void k_scatter(const int* __restrict__ idx, const float* __restrict__ vals) {
    int e = blockIdx.x * blockDim.x + threadIdx.x;
    if (e < EE) {
        int r = idx[e];
        int p = atomicAdd(&g_pos[r], 1);
        g_cv[p] = make_int2(idx[EE + e], __float_as_int(vals[e]));
    }
}

// ---------------- fp16 tensor-core GEMM (m16n8k16), BK=64, double-buffered ----------------
#define AH_LD 72
#define AH_BUF (128 * AH_LD)
#define GH_SMEM_BYTES (4 * AH_BUF * 2)  // 73728 B

__global__ __launch_bounds__(256, 2)
void k_gemm_h(const __half* __restrict__ A, int lda,
              const __half* __restrict__ Bt,
              const float* __restrict__ bias,
              __half* __restrict__ C0h,
              __half* __restrict__ Hout,
              int M, int K, int do_relu)
{
    extern __shared__ __half smh[];
    __half* As = smh;
    __half* Bs = smh + 2 * AH_BUF;

    const int nb = blockIdx.x;
    const __half* B = Bt + (size_t)nb * 128 * K;
    const float* bi = bias ? (bias + nb * 128) : (const float*)0;

    const int m0   = blockIdx.y * 128;
    const int tid  = threadIdx.x;
    const int lane = tid & 31;
    const int wid  = tid >> 5;
    const int wm0  = (wid & 1) * 64;
    const int wn0  = (wid >> 1) * 32;
    const int gp   = lane >> 2;
    const int tg   = lane & 3;

    float acc[4][4][4];
    #pragma unroll
    for (int i = 0; i < 4; i++)
        #pragma unroll
        for (int j = 0; j < 4; j++)
            #pragma unroll
            for (int q = 0; q < 4; q++) acc[i][j][q] = 0.f;

    const int nk = K >> 6;

    auto stage = [&](int kt, int buf) {
        const int k0 = kt << 6;
        uint32_t abase = (uint32_t)__cvta_generic_to_shared(As + buf * AH_BUF);
        uint32_t bbase = (uint32_t)__cvta_generic_to_shared(Bs + buf * AH_BUF);
        #pragma unroll
        for (int s = 0; s < 4; s++) {
            int idx = s * 256 + tid;
            int r = idx >> 3;
            int c = (idx & 7) * 8;
            int gr = m0 + r;
            int ok = gr < M;
            int sr = ok ? gr : (M - 1);
            cpa16(abase + (r * AH_LD + c) * 2, A + (size_t)sr * lda + k0 + c, ok);
        }
        #pragma unroll
        for (int s = 0; s < 4; s++) {
            int idx = s * 256 + tid;
            int r = idx >> 3;
            int c = (idx & 7) * 8;
            cpa16(bbase + (r * AH_LD + c) * 2, B + (size_t)r * K + k0 + c, 1);
        }
        cpa_commit();
    };

    stage(0, 0);

    for (int kt = 0; kt < nk; kt++) {
        cpa_wait0();
        __syncthreads();
        if (kt + 1 < nk) stage(kt + 1, (kt + 1) & 1);

        const __half* Ab = As + (kt & 1) * AH_BUF;
        const __half* Bb = Bs + (kt & 1) * AH_BUF;

        #pragma unroll
        for (int ks = 0; ks < 4; ks++) {
            const int kk = ks * 16 + 2 * tg;
            uint32_t af[4][4], bf[4][2];
            #pragma unroll
            for (int i = 0; i < 4; i++) {
                int r = wm0 + i * 16 + gp;
                af[i][0] = *(const uint32_t*)&Ab[r * AH_LD + kk];
                af[i][1] = *(const uint32_t*)&Ab[(r + 8) * AH_LD + kk];
                af[i][2] = *(const uint32_t*)&Ab[r * AH_LD + kk + 8];
                af[i][3] = *(const uint32_t*)&Ab[(r + 8) * AH_LD + kk + 8];
            }
            #pragma unroll
            for (int j = 0; j < 4; j++) {
                int n = wn0 + j * 8 + gp;
                bf[j][0] = *(const uint32_t*)&Bb[n * AH_LD + kk];
                bf[j][1] = *(const uint32_t*)&Bb[n * AH_LD + kk + 8];
            }
            #pragma unroll
            for (int i = 0; i < 4; i++)
                #pragma unroll
                for (int j = 0; j < 4; j++)
                    mma_f16(acc[i][j], af[i], bf[j]);
        }
        __syncthreads();
    }

    #pragma unroll
    for (int i = 0; i < 4; i++) {
        #pragma unroll
        for (int rr = 0; rr < 2; rr++) {
            int row = m0 + wm0 + i * 16 + gp + rr * 8;
            if (row >= M) continue;
            #pragma unroll
            for (int j = 0; j < 4; j++) {
                int col = wn0 + j * 8 + 2 * tg;
                float2 v;
                v.x = acc[i][j][rr * 2 + 0];
                v.y = acc[i][j][rr * 2 + 1];
                if (bi) { v.x += bi[col]; v.y += bi[col + 1]; }
                if (do_relu) { v.x = fmaxf(v.x, 0.f); v.y = fmaxf(v.y, 0.f); }
                __half2 h = __floats2half2_rn(v.x, v.y);
                if (nb == 0) {
                    *(__half2*)(C0h + (size_t)row * LD3H + col) = h;
                } else {
                    *(__half2*)(Hout + (size_t)row * 256 + (nb - 1) * 128 + col) = h;
                }
            }
        }
    }
}

// ---------------- SpMM (CSR gather, fp16 sources, packed col/val) ----------------
#define ACC8(av, hv, vv) do { \
    const __half2* _h = (const __half2*)&(hv); \
    _Pragma("unroll") \
    for (int _k = 0; _k < 4; _k++) { \
        float2 _f = __half22float2(_h[_k]); \
        (av)[2 * _k]     = fmaf((vv), _f.x, (av)[2 * _k]); \
        (av)[2 * _k + 1] = fmaf((vv), _f.y, (av)[2 * _k + 1]); \
    } \
} while (0)

// 256-wide: lane reads 8 halves (16B); unroll x8/x2/x1.
__global__ void k_spmm256t(const __half* __restrict__ src,
                           __half* __restrict__ dstH1, __half* __restrict__ dstH2)
{
    int warp = (blockIdx.x * blockDim.x + threadIdx.x) >> 5;
    int lane = threadIdx.x & 31;
    if (warp >= NN) return;
    int s = g_rowptr[warp];
    int e = g_rowptr[warp + 1];
    float a[8];
    #pragma unroll
    for (int q = 0; q < 8; q++) a[q] = 0.f;
    int p = s;
    for (; p + 7 < e; p += 8) {
        int2 cv0 = g_cv[p],     cv1 = g_cv[p + 1];
        int2 cv2 = g_cv[p + 2], cv3 = g_cv[p + 3];
        int2 cv4 = g_cv[p + 4], cv5 = g_cv[p + 5];
        int2 cv6 = g_cv[p + 6], cv7 = g_cv[p + 7];
        uint4 q0 = *(const uint4*)(src + (size_t)cv0.x * 256 + lane * 8);
        uint4 q1 = *(const uint4*)(src + (size_t)cv1.x * 256 + lane * 8);
        uint4 q2 = *(const uint4*)(src + (size_t)cv2.x * 256 + lane * 8);
        uint4 q3 = *(const uint4*)(src + (size_t)cv3.x * 256 + lane * 8);
        uint4 q4 = *(const uint4*)(src + (size_t)cv4.x * 256 + lane * 8);
        uint4 q5 = *(const uint4*)(src + (size_t)cv5.x * 256 + lane * 8);
        uint4 q6 = *(const uint4*)(src + (size_t)cv6.x * 256 + lane * 8);
        uint4 q7 = *(const uint4*)(src + (size_t)cv7.x * 256 + lane * 8);
        ACC8(a, q0, __int_as_float(cv0.y)); ACC8(a, q1, __int_as_float(cv1.y));
        ACC8(a, q2, __int_as_float(cv2.y)); ACC8(a, q3, __int_as_float(cv3.y));
        ACC8(a, q4, __int_as_float(cv4.y)); ACC8(a, q5, __int_as_float(cv5.y));
        ACC8(a, q6, __int_as_float(cv6.y)); ACC8(a, q7, __int_as_float(cv7.y));
    }
    for (; p + 1 < e; p += 2) {
        int2 cv0 = g_cv[p], cv1 = g_cv[p + 1];
        uint4 q0 = *(const uint4*)(src + (size_t)cv0.x * 256 + lane * 8);
        uint4 q1 = *(const uint4*)(src + (size_t)cv1.x * 256 + lane * 8);
        ACC8(a, q0, __int_as_float(cv0.y)); ACC8(a, q1, __int_as_float(cv1.y));
    }
    if (p < e) {
        int2 cv0 = g_cv[p];
        uint4 q0 = *(const uint4*)(src + (size_t)cv0.x * 256 + lane * 8);
        ACC8(a, q0, __int_as_float(cv0.y));
    }
    __half2 h[4];
    #pragma unroll
    for (int k = 0; k < 4; k++) h[k] = __floats2half2_rn(a[2 * k], a[2 * k + 1]);
    if (lane < 16) {
        *(uint4*)(dstH1 + (size_t)warp * LD3H + lane * 8) = *(uint4*)h;
    } else {
        *(uint4*)(dstH2 + (size_t)warp * 128 + (lane - 16) * 8) = *(uint4*)h;
    }
}

// 128-wide: 2 rows per warp (16 lanes x 8 halves); unroll x4. Plain version (stage-1).
__global__ void k_spmm128t(const __half* __restrict__ src, __half* __restrict__ dstH)
{
    int warp = (blockIdx.x * blockDim.x + threadIdx.x) >> 5;
    int lane = threadIdx.x & 31;
    int row = 2 * warp + (lane >> 4);
    int sub = lane & 15;
    if (row >= NN) return;
    int s = g_rowptr[row];
    int e = g_rowptr[row + 1];
    float a[8];
    #pragma unroll
    for (int q = 0; q < 8; q++) a[q] = 0.f;
    int p = s;
    for (; p + 3 < e; p += 4) {
        int2 cv0 = g_cv[p],     cv1 = g_cv[p + 1];
        int2 cv2 = g_cv[p + 2], cv3 = g_cv[p + 3];
        uint4 q0 = *(const uint4*)(src + (size_t)cv0.x * 128 + sub * 8);
        uint4 q1 = *(const uint4*)(src + (size_t)cv1.x * 128 + sub * 8);
        uint4 q2 = *(const uint4*)(src + (size_t)cv2.x * 128 + sub * 8);
        uint4 q3 = *(const uint4*)(src + (size_t)cv3.x * 128 + sub * 8);
        ACC8(a, q0, __int_as_float(cv0.y)); ACC8(a, q1, __int_as_float(cv1.y));
        ACC8(a, q2, __int_as_float(cv2.y)); ACC8(a, q3, __int_as_float(cv3.y));
    }
    for (; p < e; p++) {
        int2 cv0 = g_cv[p];
        uint4 q0 = *(const uint4*)(src + (size_t)cv0.x * 128 + sub * 8);
        ACC8(a, q0, __int_as_float(cv0.y));
    }
    __half2 h[4];
    #pragma unroll
    for (int k = 0; k < 4; k++) h[k] = __floats2half2_rn(a[2 * k], a[2 * k + 1]);
    *(uint4*)(dstH + (size_t)row * LD3H + sub * 8) = *(uint4*)h;
}

// ---------------- fused: stage-2 spmm128 (block2) + final log-softmax ----------------
// 128 threads = 4 warps = 8 rows per block. Phase 1: each warp computes block2 hop
// for its 2 rows into smem (+b2), and all threads load block0/1 from g2h (+b2).
// Phase 2: 384x16 matvec + log-softmax (identical to k_final16).
__global__ __launch_bounds__(128)
void k_spmm128f(const __half* __restrict__ src,       // h16C (ld 128)
                const __half* __restrict__ g,         // g2h blocks 0,1 (ld 384)
                const float* __restrict__ b2,
                const float* __restrict__ wf,
                const float* __restrict__ bfv,
                float* __restrict__ out)
{
    __shared__ float wfs[LD3H * CC];
    __shared__ float gs[8][LD3H];
    int tid = threadIdx.x;
    int lane = tid & 31;
    int wid = tid >> 5;
    int row0 = blockIdx.x * 8;

    for (int i = tid; i < LD3H * CC; i += 128) wfs[i] = wf[i];

    // blocks 0,1 from g2h (cols 0..255): 128 half2 per row
    for (int j = tid; j < 8 * 128; j += 128) {
        int r = j >> 7;
        int c = 2 * (j & 127);
        int gr = row0 + r;
        float2 f = make_float2(0.f, 0.f);
        if (gr < NN) {
            __half2 h = *(const __half2*)(g + (size_t)gr * LD3H + c);
            f = __half22float2(h);
            f.x += b2[c];
            f.y += b2[c + 1];
        }
        gs[r][c] = f.x;
        gs[r][c + 1] = f.y;
    }

    // block2 hop: warp handles rows 2*wid, 2*wid+1 (16 lanes x 8 cols each)
    {
        int lr = 2 * wid + (lane >> 4);
        int sub = lane & 15;
        int gr = row0 + lr;
        float a[8];
        #pragma unroll
        for (int q = 0; q < 8; q++) a[q] = 0.f;
        if (gr < NN) {
            int s = g_rowptr[gr];
            int e = g_rowptr[gr + 1];
            int p = s;
            for (; p + 3 < e; p += 4) {
                int2 cv0 = g_cv[p],     cv1 = g_cv[p + 1];
                int2 cv2 = g_cv[p + 2], cv3 = g_cv[p + 3];
                uint4 q0 = *(const uint4*)(src + (size_t)cv0.x * 128 + sub * 8);
                uint4 q1 = *(const uint4*)(src + (size_t)cv1.x * 128 + sub * 8);
                uint4 q2 = *(const uint4*)(src + (size_t)cv2.x * 128 + sub * 8);
                uint4 q3 = *(const uint4*)(src + (size_t)cv3.x * 128 + sub * 8);
                ACC8(a, q0, __int_as_float(cv0.y)); ACC8(a, q1, __int_as_float(cv1.y));
                ACC8(a, q2, __int_as_float(cv2.y)); ACC8(a, q3, __int_as_float(cv3.y));
            }
            for (; p < e; p++) {
                int2 cv0 = g_cv[p];
                uint4 q0 = *(const uint4*)(src + (size_t)cv0.x * 128 + sub * 8);
                ACC8(a, q0, __int_as_float(cv0.y));
            }
        }
        int cbase = 256 + sub * 8;
        #pragma unroll
        for (int q = 0; q < 8; q++) gs[lr][cbase + q] = a[q] + b2[cbase + q];
    }
    __syncthreads();

    int r = tid >> 4;
    int c = tid & 15;
    float acc = bfv[c];
    #pragma unroll 8
    for (int k = 0; k < LD3H; k++) acc = fmaf(gs[r][k], wfs[k * CC + c], acc);

    float m = acc;
    #pragma unroll
    for (int o = 8; o >= 1; o >>= 1) m = fmaxf(m, __shfl_xor_sync(0xffffffffu, m, o, 16));
    float ex = __expf(acc - m);
    float s = ex;
    #pragma unroll
    for (int o = 8; o >= 1; o >>= 1) s += __shfl_xor_sync(0xffffffffu, s, o, 16);
    int gr = row0 + r;
    if (gr < NN) out[gr * CC + c] = acc - m - logf(s);
}

// ---------------- launch ----------------
extern "C" void kernel_launch(void* const* d_in, const int* in_sizes, int n_in,
                              void* d_out, int out_size)
{
    const float* x   = (const float*)d_in[0];
    const int*   adj = (const int*)d_in[1];
    const float* av  = (const float*)d_in[2];
    const float* w1  = (const float*)d_in[3];
    const float* b1  = (const float*)d_in[4];
    const float* w2  = (const float*)d_in[5];
    const float* b2  = (const float*)d_in[6];
    const float* wf  = (const float*)d_in[7];
    const float* bf  = (const float*)d_in[8];
    float* out = (float*)d_out;

    __half *xh, *a1h, *g2h, *h16B, *h16C, *w1h, *w2h;
    cudaGetSymbolAddress((void**)&xh,   g_xh);
    cudaGetSymbolAddress((void**)&a1h,  g_a1h);
    cudaGetSymbolAddress((void**)&g2h,  g_g2h);
    cudaGetSymbolAddress((void**)&h16B, g_h16B);
    cudaGetSymbolAddress((void**)&h16C, g_h16C);
    cudaGetSymbolAddress((void**)&w1h,  g_w1h);
    cudaGetSymbolAddress((void**)&w2h,  g_w2h);

    cudaFuncSetAttribute(k_gemm_h, cudaFuncAttributeMaxDynamicSharedMemorySize,
                         GH_SMEM_BYTES);

    static cudaStream_t s2 = 0;
    static cudaEvent_t evFork = 0, evW = 0, evCSR = 0;
    if (!s2) {
        cudaStreamCreateWithFlags(&s2, cudaStreamNonBlocking);
        cudaEventCreateWithFlags(&evFork, cudaEventDisableTiming);
        cudaEventCreateWithFlags(&evW,    cudaEventDisableTiming);
        cudaEventCreateWithFlags(&evCSR,  cudaEventDisableTiming);
    }

    const int nscan = (NN + SCAN_B - 1) / SCAN_B;   // 49
    const int mtiles = (NN + 127) / 128;            // 391
    const int sblocks = (NN + 3) / 4;               // spmm256: warp per row
    const int sblocks2 = (NN / 2 + 3) / 4;          // spmm128: warp per 2 rows
    const int fblocks = (NN + 7) / 8;               // fused final: 8 rows per block

    // ---- fork: weights then CSR on s2 ----
    cudaEventRecord(evFork, 0);
    cudaStreamWaitEvent(s2, evFork, 0);
    k_wth2<<<dim3(F_IN / 32, 4, 6), dim3(32, 8), 0, s2>>>(w1, w2);
    cudaEventRecord(evW, s2);
    k_zero_counts<<<(NN + 255) / 256, 256, 0, s2>>>();
    k_count<<<(EE + 255) / 256, 256, 0, s2>>>(adj);
    k_scan1<<<nscan, SCAN_B, 0, s2>>>();
    k_scan2<<<1, 32, 0, s2>>>(nscan);
    k_scan3<<<nscan, SCAN_B, 0, s2>>>();
    k_scatter<<<(EE + 255) / 256, 256, 0, s2>>>(adj, av);
    cudaEventRecord(evCSR, s2);

    // s0: x -> fp16 (overlaps s2 prep/CSR)
    k_xhalf<<<(unsigned)((NXE / 8 + 255) / 256), 256>>>((const float4*)x);

    // GEMM1 (needs w1h)
    cudaStreamWaitEvent(0, evW, 0);
    k_gemm_h<<<dim3(3, mtiles), 256, GH_SMEM_BYTES>>>(
        xh, F_IN, w1h, b1, a1h, h16B, NN, F_IN, 1);

    // join: spmm needs CSR
    cudaStreamWaitEvent(0, evCSR, 0);

    // stage-1 hops
    k_spmm256t<<<sblocks, 128>>>(h16B, a1h + HH, h16C);
    k_spmm128t<<<sblocks2, 128>>>(h16C, a1h + 2 * HH);

    // GEMM2: block0 -> g2h; blocks 1,2 -> h16B (bias deferred)
    k_gemm_h<<<dim3(3, mtiles), 256, GH_SMEM_BYTES>>>(
        a1h, LD3H, w2h, (const float*)0, g2h, h16B, NN, LD3H, 0);

    // stage-2: spmm256 (block1 -> g2h, block2-hop1 -> h16C), then fused spmm+final
    k_spmm256t<<<sblocks, 128>>>(h16B, g2h + HH, h16C);
    k_spmm128f<<<fblocks, 128>>>(h16C, g2h, b2, wf, bf, out);

    (void)in_sizes; (void)n_in; (void)out_size;
}